// round 12
// baseline (speedup 1.0000x reference)
#include <cuda_runtime.h>
#include <cuda_fp16.h>
#include <cstdint>

// Problem dims (fixed by the dataset)
#define T_DIM 2048
#define O_DIM 4096
#define I_DIM 4096
#define R_DIM 16
#define QB    32

// Scratch: fp16 copies of W (dequant + LoRA folded) and x.
__device__ __align__(16) __half g_Wh[(size_t)O_DIM * I_DIM]; // 32 MB
__device__ __align__(16) __half g_Xh[(size_t)T_DIM * I_DIM]; // 16 MB

// ---------------------------------------------------------------------------
// Kernel 1 (merged): blocks [0,4096)   : x fp32 -> fp16 (8 elems/thread)
//                    blocks [4096,6144): W_fp16 = (q-8)*scale + alpha*up@down
// ---------------------------------------------------------------------------
#define CVT_BLOCKS  4096
#define PREP_BLOCKS 2048

__global__ void prep_all_kernel(const float* __restrict__ x,
                                const int* __restrict__ q,
                                const float* __restrict__ scales,
                                const float* __restrict__ up,
                                const float* __restrict__ down,
                                const float* __restrict__ alpha_p) {
    if (blockIdx.x < CVT_BLOCKS) {
        size_t i = ((size_t)blockIdx.x * blockDim.x + threadIdx.x) * 8;
        float4 v0 = *(const float4*)(x + i);
        float4 v1 = *(const float4*)(x + i + 4);
        *(__half2*)(g_Xh + i)     = __floats2half2_rn(v0.x, v0.y);
        *(__half2*)(g_Xh + i + 2) = __floats2half2_rn(v0.z, v0.w);
        *(__half2*)(g_Xh + i + 4) = __floats2half2_rn(v1.x, v1.y);
        *(__half2*)(g_Xh + i + 6) = __floats2half2_rn(v1.z, v1.w);
        return;
    }
    const int igroups = I_DIM / 4; // 1024
    size_t gt = (size_t)(blockIdx.x - CVT_BLOCKS) * blockDim.x + threadIdx.x;
    int ig = (int)(gt % igroups);
    int ob = (int)(gt / igroups) * 8;
    int i  = ig * 4;
    float alpha = *alpha_p;

    float4 dsum[8];
#pragma unroll
    for (int j = 0; j < 8; ++j) dsum[j] = make_float4(0.f, 0.f, 0.f, 0.f);

#pragma unroll
    for (int r = 0; r < R_DIM; ++r) {
        float4 dv = *(const float4*)(down + (size_t)r * I_DIM + i);
#pragma unroll
        for (int j = 0; j < 8; ++j) {
            float u = up[(size_t)(ob + j) * R_DIM + r];
            dsum[j].x += u * dv.x;
            dsum[j].y += u * dv.y;
            dsum[j].z += u * dv.z;
            dsum[j].w += u * dv.w;
        }
    }

#pragma unroll
    for (int j = 0; j < 8; ++j) {
        int o = ob + j;
        size_t base = (size_t)o * I_DIM + i;
        int4 qv = *(const int4*)(q + base);
        float s = scales[(size_t)o * (I_DIM / QB) + (i >> 5)];
        float w0 = (float)(qv.x - 8) * s + alpha * dsum[j].x;
        float w1 = (float)(qv.y - 8) * s + alpha * dsum[j].y;
        float w2 = (float)(qv.z - 8) * s + alpha * dsum[j].z;
        float w3 = (float)(qv.w - 8) * s + alpha * dsum[j].w;
        *(__half2*)(g_Wh + base)     = __floats2half2_rn(w0, w1);
        *(__half2*)(g_Wh + base + 2) = __floats2half2_rn(w2, w3);
    }
}

// ---------------------------------------------------------------------------
// Kernel 2: GEMM  y[t,o] = sum_k Xh[t,k]*Wh[o,k] + bias[o]
// CTA tile 128x256x64, 512 thr = 16 warps (4M x 4N), warp tile 32x64.
// fp16-accumulator mma (rt=4 hypothesis), promoted to fp32 every 2 k-tiles
// (K=128 chunks). 4-stage cp.async pipeline (wait_group 2).
// ---------------------------------------------------------------------------
#define GBM 128
#define GBN 256
#define GBK 64
#define NKT (I_DIM / GBK)        // 64
#define LDSH 72                  // halves per smem row (144 B, conflict-free)
#define A_STAGE_H (GBM * LDSH)
#define B_STAGE_H (GBN * LDSH)
#define STAGE_H   (A_STAGE_H + B_STAGE_H)
#define NSTAGE 4
#define DYN_SMEM_BYTES (NSTAGE * STAGE_H * 2)  // 221,184 B
#define GTHREADS 512

__device__ __forceinline__ uint32_t smem_u32(const void* p) {
    return (uint32_t)__cvta_generic_to_shared(p);
}
__device__ __forceinline__ void cp_async16(uint32_t s, const void* g) {
    asm volatile("cp.async.cg.shared.global [%0], [%1], 16;" :: "r"(s), "l"(g));
}
__device__ __forceinline__ void ldsm_x4(uint32_t* r, uint32_t addr) {
    asm volatile("ldmatrix.sync.aligned.m8n8.x4.shared.b16 {%0,%1,%2,%3}, [%4];"
                 : "=r"(r[0]), "=r"(r[1]), "=r"(r[2]), "=r"(r[3]) : "r"(addr));
}
// fp16-accumulator mma: D,C are 2 b32 regs (4 packed halves)
__device__ __forceinline__ void mma_16816_h(uint32_t* c, const uint32_t* a, const uint32_t* b) {
    asm volatile(
        "mma.sync.aligned.m16n8k16.row.col.f16.f16.f16.f16 "
        "{%0,%1}, {%2,%3,%4,%5}, {%6,%7}, {%0,%1};\n"
        : "+r"(c[0]), "+r"(c[1])
        : "r"(a[0]), "r"(a[1]), "r"(a[2]), "r"(a[3]), "r"(b[0]), "r"(b[1]));
}

__global__ void __launch_bounds__(GTHREADS, 1) gemm_kernel(const float* __restrict__ bias,
                                                           float* __restrict__ y) {
    extern __shared__ __half smem[];

    const int tid  = threadIdx.x;
    const int lane = tid & 31;
    const int warp = tid >> 5;
    const int wm = warp >> 2;  // 0..3 (M, 32 rows)
    const int wn = warp & 3;   // 0..3 (N, 64 cols)

    const size_t bmOff = (size_t)blockIdx.y * GBM;
    const size_t bnOff = (size_t)blockIdx.x * GBN;
    const __half* gA = g_Xh + bmOff * I_DIM;
    const __half* gB = g_Wh + bnOff * I_DIM;

    const int lrow = tid >> 3;       // 0..63
    const int ach  = (tid & 7) * 8;

    auto issue_stage = [&](int kt, int stg) {
        __half* sa = smem + stg * STAGE_H;
        __half* sb = sa + A_STAGE_H;
        const __half* gAk = gA + kt * GBK;
        const __half* gBk = gB + kt * GBK;
#pragma unroll
        for (int j = 0; j < 2; ++j) {
            int row = lrow + j * 64;            // 0..127
            cp_async16(smem_u32(sa + row * LDSH + ach),
                       gAk + (size_t)row * I_DIM + ach);
        }
#pragma unroll
        for (int j = 0; j < 4; ++j) {
            int row = lrow + j * 64;            // 0..255
            cp_async16(smem_u32(sb + row * LDSH + ach),
                       gBk + (size_t)row * I_DIM + ach);
        }
    };

    float facc[2][8][4];        // fp32 master accumulators
    uint32_t hacc[2][8][2];     // fp16 chunk accumulators (packed)
#pragma unroll
    for (int a = 0; a < 2; ++a)
#pragma unroll
        for (int b = 0; b < 8; ++b) {
#pragma unroll
            for (int c = 0; c < 4; ++c) facc[a][b][c] = 0.f;
            hacc[a][b][0] = 0u; hacc[a][b][1] = 0u;
        }

    // prologue: fill stages 0..2
    issue_stage(0, 0);
    asm volatile("cp.async.commit_group;" ::: "memory");
    issue_stage(1, 1);
    asm volatile("cp.async.commit_group;" ::: "memory");
    issue_stage(2, 2);
    asm volatile("cp.async.commit_group;" ::: "memory");

    // ldsm lane addressing
    const int a_r = (lane & 15);
    const int a_c = (lane >> 4) * 8;
    const int bg  = lane >> 3;                     // 0..3
    const int b_r = ((bg >> 1) * 8) + (lane & 7);
    const int b_c = (bg & 1) * 8;

    for (int kt = 0; kt < NKT; ++kt) {
        const int stg = kt & 3;
        asm volatile("cp.async.wait_group 2;" ::: "memory");
        __syncthreads();

        if (kt + 3 < NKT) issue_stage(kt + 3, (kt + 3) & 3);
        asm volatile("cp.async.commit_group;" ::: "memory");

        const __half* sa = smem + stg * STAGE_H;
        const __half* sb = sa + A_STAGE_H;
#pragma unroll
        for (int ks = 0; ks < 4; ++ks) {
            uint32_t afr[2][4], bfr[8][2];
#pragma unroll
            for (int mi = 0; mi < 2; ++mi) {
                uint32_t ad = smem_u32(sa + (wm * 32 + mi * 16 + a_r) * LDSH
                                          + ks * 16 + a_c);
                ldsm_x4(afr[mi], ad);
            }
#pragma unroll
            for (int nq = 0; nq < 4; ++nq) {
                uint32_t r[4];
                uint32_t bd = smem_u32(sb + (wn * 64 + nq * 16 + b_r) * LDSH
                                          + ks * 16 + b_c);
                ldsm_x4(r, bd);
                bfr[nq * 2 + 0][0] = r[0]; bfr[nq * 2 + 0][1] = r[1];
                bfr[nq * 2 + 1][0] = r[2]; bfr[nq * 2 + 1][1] = r[3];
            }
#pragma unroll
            for (int mi = 0; mi < 2; ++mi)
#pragma unroll
                for (int ni = 0; ni < 8; ++ni)
                    mma_16816_h(hacc[mi][ni], afr[mi], bfr[ni]);
        }

        // Promote fp16 chunk -> fp32 every 2 k-tiles (K=128 per chunk)
        if (kt & 1) {
#pragma unroll
            for (int mi = 0; mi < 2; ++mi)
#pragma unroll
                for (int ni = 0; ni < 8; ++ni) {
                    float2 lo = __half22float2(*(__half2*)&hacc[mi][ni][0]);
                    float2 hi = __half22float2(*(__half2*)&hacc[mi][ni][1]);
                    facc[mi][ni][0] += lo.x;
                    facc[mi][ni][1] += lo.y;
                    facc[mi][ni][2] += hi.x;
                    facc[mi][ni][3] += hi.y;
                    hacc[mi][ni][0] = 0u;
                    hacc[mi][ni][1] = 0u;
                }
        }
    }

    // Epilogue: fused bias add, float2 stores.
    const int gid = lane >> 2, tig = lane & 3;
#pragma unroll
    for (int mi = 0; mi < 2; ++mi) {
        const size_t row = bmOff + wm * 32 + mi * 16 + gid;
#pragma unroll
        for (int ni = 0; ni < 8; ++ni) {
            const int col = (int)bnOff + wn * 64 + ni * 8 + tig * 2;
            float2 bv = *(const float2*)(bias + col);
            float2 o0 = make_float2(facc[mi][ni][0] + bv.x, facc[mi][ni][1] + bv.y);
            float2 o1 = make_float2(facc[mi][ni][2] + bv.x, facc[mi][ni][3] + bv.y);
            *(float2*)(y + row * O_DIM + col)       = o0;
            *(float2*)(y + (row + 8) * O_DIM + col) = o1;
        }
    }
}

// ---------------------------------------------------------------------------
extern "C" void kernel_launch(void* const* d_in, const int* in_sizes, int n_in,
                              void* d_out, int out_size) {
    const float* x      = (const float*)d_in[0];
    const int*   q      = (const int*)d_in[1];
    const float* scales = (const float*)d_in[2];
    const float* up     = (const float*)d_in[3];
    const float* down   = (const float*)d_in[4];
    const float* alpha  = (const float*)d_in[5];
    const float* bias   = (const float*)d_in[6];
    float* y = (float*)d_out;
    (void)in_sizes; (void)n_in; (void)out_size;

    // 1) x -> fp16 AND dequant+LoRA -> fp16 W (merged)
    prep_all_kernel<<<CVT_BLOCKS + PREP_BLOCKS, 256>>>(x, q, scales, up, down, alpha);
    // 2) fp16 tensor-core GEMM (fp16 acc + fp32 promotion) + bias
    cudaFuncSetAttribute(gemm_kernel, cudaFuncAttributeMaxDynamicSharedMemorySize,
                         DYN_SMEM_BYTES);
    dim3 grid(O_DIM / GBN, T_DIM / GBM);  // (16, 16)
    gemm_kernel<<<grid, GTHREADS, DYN_SMEM_BYTES>>>(bias, y);
}

// round 13
// speedup vs baseline: 1.4608x; 1.4608x over previous
#include <cuda_runtime.h>
#include <cuda_fp16.h>
#include <cstdint>

// Problem dims (fixed by the dataset)
#define T_DIM 2048
#define O_DIM 4096
#define I_DIM 4096
#define R_DIM 16
#define QB    32

// Scratch: fp16 copies of W (dequant + LoRA folded) and x.
__device__ __align__(16) __half g_Wh[(size_t)O_DIM * I_DIM]; // 32 MB
__device__ __align__(16) __half g_Xh[(size_t)T_DIM * I_DIM]; // 16 MB

// ---------------------------------------------------------------------------
// Kernel 1: x (fp32) -> fp16   (8 elems / thread)
// ---------------------------------------------------------------------------
__global__ void cvt_x_kernel(const float* __restrict__ x) {
    size_t i = ((size_t)blockIdx.x * blockDim.x + threadIdx.x) * 8;
    float4 v0 = *(const float4*)(x + i);
    float4 v1 = *(const float4*)(x + i + 4);
    *(__half2*)(g_Xh + i)     = __floats2half2_rn(v0.x, v0.y);
    *(__half2*)(g_Xh + i + 2) = __floats2half2_rn(v0.z, v0.w);
    *(__half2*)(g_Xh + i + 4) = __floats2half2_rn(v1.x, v1.y);
    *(__half2*)(g_Xh + i + 6) = __floats2half2_rn(v1.z, v1.w);
}

// ---------------------------------------------------------------------------
// Kernel 2: W_fp16[o,i] = (q-8)*scale + alpha * up@down
// o-tile = 16 (halves per-element `down` L2 traffic vs o-tile 8), i-tile = 4.
// ---------------------------------------------------------------------------
__global__ void prep_w_kernel(const int* __restrict__ q,
                              const float* __restrict__ scales,
                              const float* __restrict__ up,
                              const float* __restrict__ down,
                              const float* __restrict__ alpha_p) {
    const int igroups = I_DIM / 4; // 1024
    size_t gt = (size_t)blockIdx.x * blockDim.x + threadIdx.x;
    int ig = (int)(gt % igroups);
    int ob = (int)(gt / igroups) * 16;
    int i  = ig * 4;
    float alpha = *alpha_p;

    float4 dsum[16];
#pragma unroll
    for (int j = 0; j < 16; ++j) dsum[j] = make_float4(0.f, 0.f, 0.f, 0.f);

#pragma unroll
    for (int r = 0; r < R_DIM; ++r) {
        float4 dv = *(const float4*)(down + (size_t)r * I_DIM + i);
#pragma unroll
        for (int j = 0; j < 16; ++j) {
            float u = __ldg(up + (size_t)(ob + j) * R_DIM + r); // uniform per block
            dsum[j].x += u * dv.x;
            dsum[j].y += u * dv.y;
            dsum[j].z += u * dv.z;
            dsum[j].w += u * dv.w;
        }
    }

#pragma unroll
    for (int j = 0; j < 16; ++j) {
        int o = ob + j;
        size_t base = (size_t)o * I_DIM + i;
        int4 qv = *(const int4*)(q + base);
        float s = scales[(size_t)o * (I_DIM / QB) + (i >> 5)];
        float w0 = (float)(qv.x - 8) * s + alpha * dsum[j].x;
        float w1 = (float)(qv.y - 8) * s + alpha * dsum[j].y;
        float w2 = (float)(qv.z - 8) * s + alpha * dsum[j].z;
        float w3 = (float)(qv.w - 8) * s + alpha * dsum[j].w;
        *(__half2*)(g_Wh + base)     = __floats2half2_rn(w0, w1);
        *(__half2*)(g_Wh + base + 2) = __floats2half2_rn(w2, w3);
    }
}

// ---------------------------------------------------------------------------
// Kernel 3: GEMM  y[t,o] = sum_k Xh[t,k]*Wh[o,k] + bias[o]
// (R11 kernel verbatim — measured at the HMMA accept-rate floor, 225.5us.)
// CTA tile 128x256x64, 256 thr = 8 warps (2M x 4N), warp tile 64x64.
// 4-stage cp.async pipeline (wait_group 2) + register double-buffered frags.
// ---------------------------------------------------------------------------
#define GBM 128
#define GBN 256
#define GBK 64
#define NKT (I_DIM / GBK)        // 64
#define LDSH 72                  // halves per smem row (144 B, conflict-free)
#define A_STAGE_H (GBM * LDSH)
#define B_STAGE_H (GBN * LDSH)
#define STAGE_H   (A_STAGE_H + B_STAGE_H)
#define NSTAGE 4
#define DYN_SMEM_BYTES (NSTAGE * STAGE_H * 2)  // 221,184 B

__device__ __forceinline__ uint32_t smem_u32(const void* p) {
    return (uint32_t)__cvta_generic_to_shared(p);
}
__device__ __forceinline__ void cp_async16(uint32_t s, const void* g) {
    asm volatile("cp.async.cg.shared.global [%0], [%1], 16;" :: "r"(s), "l"(g));
}
__device__ __forceinline__ void ldsm_x4(uint32_t* r, uint32_t addr) {
    asm volatile("ldmatrix.sync.aligned.m8n8.x4.shared.b16 {%0,%1,%2,%3}, [%4];"
                 : "=r"(r[0]), "=r"(r[1]), "=r"(r[2]), "=r"(r[3]) : "r"(addr));
}
__device__ __forceinline__ void mma_16816(float* c, const uint32_t* a, const uint32_t* b) {
    asm volatile(
        "mma.sync.aligned.m16n8k16.row.col.f32.f16.f16.f32 "
        "{%0,%1,%2,%3}, {%4,%5,%6,%7}, {%8,%9}, {%0,%1,%2,%3};\n"
        : "+f"(c[0]), "+f"(c[1]), "+f"(c[2]), "+f"(c[3])
        : "r"(a[0]), "r"(a[1]), "r"(a[2]), "r"(a[3]), "r"(b[0]), "r"(b[1]));
}

__global__ void __launch_bounds__(256, 1) gemm_kernel(const float* __restrict__ bias,
                                                      float* __restrict__ y) {
    extern __shared__ __half smem[];

    const int tid  = threadIdx.x;
    const int lane = tid & 31;
    const int warp = tid >> 5;
    const int wm = warp >> 2;  // 0..1 (M)
    const int wn = warp & 3;   // 0..3 (N)

    const size_t bmOff = (size_t)blockIdx.y * GBM;
    const size_t bnOff = (size_t)blockIdx.x * GBN;
    const __half* gA = g_Xh + bmOff * I_DIM;
    const __half* gB = g_Wh + bnOff * I_DIM;

    const int ach = (tid & 7) * 8;

    auto issue_stage = [&](int kt, int stg) {
        __half* sa = smem + stg * STAGE_H;
        __half* sb = sa + A_STAGE_H;
        const __half* gAk = gA + kt * GBK;
        const __half* gBk = gB + kt * GBK;
#pragma unroll
        for (int j = 0; j < 4; ++j) {
            int row = (tid >> 3) + j * 32;       // 0..127
            cp_async16(smem_u32(sa + row * LDSH + ach),
                       gAk + (size_t)row * I_DIM + ach);
        }
#pragma unroll
        for (int j = 0; j < 8; ++j) {
            int row = (tid >> 3) + j * 32;       // 0..255
            cp_async16(smem_u32(sb + row * LDSH + ach),
                       gBk + (size_t)row * I_DIM + ach);
        }
    };

    float acc[4][8][4];
#pragma unroll
    for (int a = 0; a < 4; ++a)
#pragma unroll
        for (int b = 0; b < 8; ++b)
#pragma unroll
            for (int c = 0; c < 4; ++c) acc[a][b][c] = 0.f;

    // prologue: fill stages 0..2
    issue_stage(0, 0);
    asm volatile("cp.async.commit_group;" ::: "memory");
    issue_stage(1, 1);
    asm volatile("cp.async.commit_group;" ::: "memory");
    issue_stage(2, 2);
    asm volatile("cp.async.commit_group;" ::: "memory");

    // ldsm lane addressing
    const int a_r = (lane & 15);
    const int a_c = (lane >> 4) * 8;
    const int bg  = lane >> 3;                     // 0..3
    const int b_r = ((bg >> 1) * 8) + (lane & 7);
    const int b_c = (bg & 1) * 8;

    // Double-buffered fragments
    uint32_t afr[2][4][4];
    uint32_t bfr[2][8][2];

    auto load_frags = [&](const __half* sa, const __half* sb, int ks, int buf) {
#pragma unroll
        for (int mi = 0; mi < 4; ++mi) {
            uint32_t ad = smem_u32(sa + (wm * 64 + mi * 16 + a_r) * LDSH
                                      + ks * 16 + a_c);
            ldsm_x4(afr[buf][mi], ad);
        }
#pragma unroll
        for (int nq = 0; nq < 4; ++nq) {
            uint32_t r[4];
            uint32_t bd = smem_u32(sb + (wn * 64 + nq * 16 + b_r) * LDSH
                                      + ks * 16 + b_c);
            ldsm_x4(r, bd);
            bfr[buf][nq * 2 + 0][0] = r[0]; bfr[buf][nq * 2 + 0][1] = r[1];
            bfr[buf][nq * 2 + 1][0] = r[2]; bfr[buf][nq * 2 + 1][1] = r[3];
        }
    };

    for (int kt = 0; kt < NKT; ++kt) {
        const int stg = kt & 3;
        asm volatile("cp.async.wait_group 2;" ::: "memory");
        __syncthreads();

        if (kt + 3 < NKT) issue_stage(kt + 3, (kt + 3) & 3);
        asm volatile("cp.async.commit_group;" ::: "memory");

        const __half* sa = smem + stg * STAGE_H;
        const __half* sb = sa + A_STAGE_H;

        load_frags(sa, sb, 0, 0);
#pragma unroll
        for (int ks = 0; ks < 4; ++ks) {
            const int cur = ks & 1;
            if (ks < 3) load_frags(sa, sb, ks + 1, cur ^ 1);
#pragma unroll
            for (int mi = 0; mi < 4; ++mi)
#pragma unroll
                for (int ni = 0; ni < 8; ++ni)
                    mma_16816(acc[mi][ni], afr[cur][mi], bfr[cur][ni]);
        }
    }

    // Epilogue: fused bias add, float2 stores.
    const int gid = lane >> 2, tig = lane & 3;
#pragma unroll
    for (int mi = 0; mi < 4; ++mi) {
        const size_t row = bmOff + wm * 64 + mi * 16 + gid;
#pragma unroll
        for (int ni = 0; ni < 8; ++ni) {
            const int col = (int)bnOff + wn * 64 + ni * 8 + tig * 2;
            float2 bv = *(const float2*)(bias + col);
            float2 o0 = make_float2(acc[mi][ni][0] + bv.x, acc[mi][ni][1] + bv.y);
            float2 o1 = make_float2(acc[mi][ni][2] + bv.x, acc[mi][ni][3] + bv.y);
            *(float2*)(y + row * O_DIM + col)       = o0;
            *(float2*)(y + (row + 8) * O_DIM + col) = o1;
        }
    }
}

// ---------------------------------------------------------------------------
extern "C" void kernel_launch(void* const* d_in, const int* in_sizes, int n_in,
                              void* d_out, int out_size) {
    const float* x      = (const float*)d_in[0];
    const int*   q      = (const int*)d_in[1];
    const float* scales = (const float*)d_in[2];
    const float* up     = (const float*)d_in[3];
    const float* down   = (const float*)d_in[4];
    const float* alpha  = (const float*)d_in[5];
    const float* bias   = (const float*)d_in[6];
    float* y = (float*)d_out;
    (void)in_sizes; (void)n_in; (void)out_size;

    // 1) x -> fp16
    cvt_x_kernel<<<(T_DIM * I_DIM / 8) / 256, 256>>>(x);
    // 2) dequant + LoRA -> fp16 W (o-tile 16)
    prep_w_kernel<<<((I_DIM / 4) * (O_DIM / 16)) / 256, 256>>>(q, scales, up, down, alpha);
    // 3) fp16 tensor-core GEMM + bias
    cudaFuncSetAttribute(gemm_kernel, cudaFuncAttributeMaxDynamicSharedMemorySize,
                         DYN_SMEM_BYTES);
    dim3 grid(O_DIM / GBN, T_DIM / GBM);  // (16, 16)
    gemm_kernel<<<grid, 256, DYN_SMEM_BYTES>>>(bias, y);
}

// round 14
// speedup vs baseline: 1.7036x; 1.1662x over previous
#include <cuda_runtime.h>
#include <cuda_fp16.h>
#include <cstdint>

// Problem dims (fixed by the dataset)
#define T_DIM 2048
#define O_DIM 4096
#define I_DIM 4096
#define R_DIM 16
#define QB    32

// Scratch: fp16 copies of W (dequant + LoRA folded) and x.
__device__ __align__(16) __half g_Wh[(size_t)O_DIM * I_DIM]; // 32 MB
__device__ __align__(16) __half g_Xh[(size_t)T_DIM * I_DIM]; // 16 MB

// ---------------------------------------------------------------------------
// Kernel 1: blocks [0,4096)    : x fp32 -> fp16 (8 elems/thread)
//           blocks [4096,8192) : y[t,o] = bias[o]  (pre-init for atomic GEMM)
// ---------------------------------------------------------------------------
#define CVT_BLOCKS 4096

__global__ void cvt_init_kernel(const float* __restrict__ x,
                                const float* __restrict__ bias,
                                float* __restrict__ y) {
    if (blockIdx.x < CVT_BLOCKS) {
        size_t i = ((size_t)blockIdx.x * blockDim.x + threadIdx.x) * 8;
        float4 v0 = *(const float4*)(x + i);
        float4 v1 = *(const float4*)(x + i + 4);
        *(__half2*)(g_Xh + i)     = __floats2half2_rn(v0.x, v0.y);
        *(__half2*)(g_Xh + i + 2) = __floats2half2_rn(v0.z, v0.w);
        *(__half2*)(g_Xh + i + 4) = __floats2half2_rn(v1.x, v1.y);
        *(__half2*)(g_Xh + i + 6) = __floats2half2_rn(v1.z, v1.w);
    } else {
        size_t i = ((size_t)(blockIdx.x - CVT_BLOCKS) * blockDim.x + threadIdx.x) * 8;
        int o = (int)(i & (O_DIM - 1));      // 8-aligned within a row
        float4 b0 = *(const float4*)(bias + o);
        float4 b1 = *(const float4*)(bias + o + 4);
        *(float4*)(y + i)     = b0;
        *(float4*)(y + i + 4) = b1;
    }
}

// ---------------------------------------------------------------------------
// Kernel 2: W_fp16[o,i] = (q-8)*scale + alpha * up@down   (R9 version, o-tile 8)
// ---------------------------------------------------------------------------
__global__ void prep_w_kernel(const int* __restrict__ q,
                              const float* __restrict__ scales,
                              const float* __restrict__ up,
                              const float* __restrict__ down,
                              const float* __restrict__ alpha_p) {
    const int igroups = I_DIM / 4; // 1024
    size_t gt = (size_t)blockIdx.x * blockDim.x + threadIdx.x;
    int ig = (int)(gt % igroups);
    int ob = (int)(gt / igroups) * 8;
    int i  = ig * 4;
    float alpha = *alpha_p;

    float4 dsum[8];
#pragma unroll
    for (int j = 0; j < 8; ++j) dsum[j] = make_float4(0.f, 0.f, 0.f, 0.f);

#pragma unroll
    for (int r = 0; r < R_DIM; ++r) {
        float4 dv = *(const float4*)(down + (size_t)r * I_DIM + i);
#pragma unroll
        for (int j = 0; j < 8; ++j) {
            float u = up[(size_t)(ob + j) * R_DIM + r];
            dsum[j].x += u * dv.x;
            dsum[j].y += u * dv.y;
            dsum[j].z += u * dv.z;
            dsum[j].w += u * dv.w;
        }
    }

#pragma unroll
    for (int j = 0; j < 8; ++j) {
        int o = ob + j;
        size_t base = (size_t)o * I_DIM + i;
        int4 qv = *(const int4*)(q + base);
        float s = scales[(size_t)o * (I_DIM / QB) + (i >> 5)];
        float w0 = (float)(qv.x - 8) * s + alpha * dsum[j].x;
        float w1 = (float)(qv.y - 8) * s + alpha * dsum[j].y;
        float w2 = (float)(qv.z - 8) * s + alpha * dsum[j].z;
        float w3 = (float)(qv.w - 8) * s + alpha * dsum[j].w;
        *(__half2*)(g_Wh + base)     = __floats2half2_rn(w0, w1);
        *(__half2*)(g_Wh + base + 2) = __floats2half2_rn(w2, w3);
    }
}

// ---------------------------------------------------------------------------
// Kernel 3: PERSISTENT split-K GEMM,  y += Xh * Wh^T  (y pre-init to bias).
// 148 CTAs (1/SM). Work = 16384 units (256 tiles x 64 k-tiles); each CTA gets
// a contiguous ~110.7-unit range; tile K may split across 2 CTAs -> f32
// atomicAdd epilogue. cp.async pipeline runs continuously across tiles.
// CTA tile 128x256x64, 8 warps (2M x 4N), warp tile 64x64, 4 stages.
// ---------------------------------------------------------------------------
#define GBM 128
#define GBN 256
#define GBK 64
#define NKT (I_DIM / GBK)        // 64
#define NTILES ((T_DIM / GBM) * (O_DIM / GBN))  // 256
#define UNITS (NTILES * NKT)     // 16384
#define NCTA 148
#define LDSH 72                  // halves per smem row (144 B, conflict-free)
#define A_STAGE_H (GBM * LDSH)
#define B_STAGE_H (GBN * LDSH)
#define STAGE_H   (A_STAGE_H + B_STAGE_H)
#define NSTAGE 4
#define DYN_SMEM_BYTES (NSTAGE * STAGE_H * 2)  // 221,184 B

__device__ __forceinline__ uint32_t smem_u32(const void* p) {
    return (uint32_t)__cvta_generic_to_shared(p);
}
__device__ __forceinline__ void cp_async16(uint32_t s, const void* g) {
    asm volatile("cp.async.cg.shared.global [%0], [%1], 16;" :: "r"(s), "l"(g));
}
__device__ __forceinline__ void ldsm_x4(uint32_t* r, uint32_t addr) {
    asm volatile("ldmatrix.sync.aligned.m8n8.x4.shared.b16 {%0,%1,%2,%3}, [%4];"
                 : "=r"(r[0]), "=r"(r[1]), "=r"(r[2]), "=r"(r[3]) : "r"(addr));
}
__device__ __forceinline__ void mma_16816(float* c, const uint32_t* a, const uint32_t* b) {
    asm volatile(
        "mma.sync.aligned.m16n8k16.row.col.f32.f16.f16.f32 "
        "{%0,%1,%2,%3}, {%4,%5,%6,%7}, {%8,%9}, {%0,%1,%2,%3};\n"
        : "+f"(c[0]), "+f"(c[1]), "+f"(c[2]), "+f"(c[3])
        : "r"(a[0]), "r"(a[1]), "r"(a[2]), "r"(a[3]), "r"(b[0]), "r"(b[1]));
}

__global__ void __launch_bounds__(256, 1) gemm_kernel(float* __restrict__ y) {
    extern __shared__ __half smem[];

    const int tid  = threadIdx.x;
    const int lane = tid & 31;
    const int warp = tid >> 5;
    const int wm = warp >> 2;  // 0..1 (M)
    const int wn = warp & 3;   // 0..3 (N)

    const int u0 = (int)(((long long)blockIdx.x * UNITS) / NCTA);
    const int u1 = (int)(((long long)(blockIdx.x + 1) * UNITS) / NCTA);

    const int ach = (tid & 7) * 8;

    // issue cp.async loads for work-unit u into its stage (u & 3)
    auto issue_stage = [&](int u) {
        const int stg  = u & 3;
        const int tile = u >> 6;
        const int kt   = u & 63;
        const __half* gAk = g_Xh + (size_t)(tile >> 4) * GBM * I_DIM + kt * GBK;
        const __half* gBk = g_Wh + (size_t)(tile & 15) * GBN * I_DIM + kt * GBK;
        __half* sa = smem + stg * STAGE_H;
        __half* sb = sa + A_STAGE_H;
#pragma unroll
        for (int j = 0; j < 4; ++j) {
            int row = (tid >> 3) + j * 32;       // 0..127
            cp_async16(smem_u32(sa + row * LDSH + ach),
                       gAk + (size_t)row * I_DIM + ach);
        }
#pragma unroll
        for (int j = 0; j < 8; ++j) {
            int row = (tid >> 3) + j * 32;       // 0..255
            cp_async16(smem_u32(sb + row * LDSH + ach),
                       gBk + (size_t)row * I_DIM + ach);
        }
    };

    float acc[4][8][4];
#pragma unroll
    for (int a = 0; a < 4; ++a)
#pragma unroll
        for (int b = 0; b < 8; ++b)
#pragma unroll
            for (int c = 0; c < 4; ++c) acc[a][b][c] = 0.f;

    const int gid = lane >> 2, tig = lane & 3;
    // atomicAdd epilogue for `tile` from acc, then clear acc
    auto epilogue = [&](int tile) {
        const size_t bmOff = (size_t)(tile >> 4) * GBM;
        const size_t bnOff = (size_t)(tile & 15) * GBN;
#pragma unroll
        for (int mi = 0; mi < 4; ++mi) {
            const size_t row = bmOff + wm * 64 + mi * 16 + gid;
            float* y0 = y + row * O_DIM;
            float* y1 = y + (row + 8) * O_DIM;
#pragma unroll
            for (int ni = 0; ni < 8; ++ni) {
                const int col = (int)bnOff + wn * 64 + ni * 8 + tig * 2;
                atomicAdd(y0 + col,     acc[mi][ni][0]);
                atomicAdd(y0 + col + 1, acc[mi][ni][1]);
                atomicAdd(y1 + col,     acc[mi][ni][2]);
                atomicAdd(y1 + col + 1, acc[mi][ni][3]);
                acc[mi][ni][0] = 0.f; acc[mi][ni][1] = 0.f;
                acc[mi][ni][2] = 0.f; acc[mi][ni][3] = 0.f;
            }
        }
    };

    // prologue: fill 3 stages
    issue_stage(u0);
    asm volatile("cp.async.commit_group;" ::: "memory");
    if (u0 + 1 < u1) issue_stage(u0 + 1);
    asm volatile("cp.async.commit_group;" ::: "memory");
    if (u0 + 2 < u1) issue_stage(u0 + 2);
    asm volatile("cp.async.commit_group;" ::: "memory");

    // ldsm lane addressing
    const int a_r = (lane & 15);
    const int a_c = (lane >> 4) * 8;
    const int bg  = lane >> 3;                     // 0..3
    const int b_r = ((bg >> 1) * 8) + (lane & 7);
    const int b_c = (bg & 1) * 8;

    // register double-buffered fragments
    uint32_t afr[2][4][4];
    uint32_t bfr[2][8][2];

    auto load_frags = [&](const __half* sa, const __half* sb, int ks, int buf) {
#pragma unroll
        for (int mi = 0; mi < 4; ++mi) {
            uint32_t ad = smem_u32(sa + (wm * 64 + mi * 16 + a_r) * LDSH
                                      + ks * 16 + a_c);
            ldsm_x4(afr[buf][mi], ad);
        }
#pragma unroll
        for (int nq = 0; nq < 4; ++nq) {
            uint32_t r[4];
            uint32_t bd = smem_u32(sb + (wn * 64 + nq * 16 + b_r) * LDSH
                                      + ks * 16 + b_c);
            ldsm_x4(r, bd);
            bfr[buf][nq * 2 + 0][0] = r[0]; bfr[buf][nq * 2 + 0][1] = r[1];
            bfr[buf][nq * 2 + 1][0] = r[2]; bfr[buf][nq * 2 + 1][1] = r[3];
        }
    };

    for (int u = u0; u < u1; ++u) {
        const int stg = u & 3;
        asm volatile("cp.async.wait_group 2;" ::: "memory");
        __syncthreads();

        if (u + 3 < u1) issue_stage(u + 3);
        asm volatile("cp.async.commit_group;" ::: "memory");

        // crossing into a new tile: flush previous tile's partial sums
        if (u != u0 && (u & 63) == 0)
            epilogue((u >> 6) - 1);

        const __half* sa = smem + stg * STAGE_H;
        const __half* sb = sa + A_STAGE_H;

        load_frags(sa, sb, 0, 0);
#pragma unroll
        for (int ks = 0; ks < 4; ++ks) {
            const int cur = ks & 1;
            if (ks < 3) load_frags(sa, sb, ks + 1, cur ^ 1);
#pragma unroll
            for (int mi = 0; mi < 4; ++mi)
#pragma unroll
                for (int ni = 0; ni < 8; ++ni)
                    mma_16816(acc[mi][ni], afr[cur][mi], bfr[cur][ni]);
        }
    }

    // flush final tile
    epilogue((u1 - 1) >> 6);
}

// ---------------------------------------------------------------------------
extern "C" void kernel_launch(void* const* d_in, const int* in_sizes, int n_in,
                              void* d_out, int out_size) {
    const float* x      = (const float*)d_in[0];
    const int*   q      = (const int*)d_in[1];
    const float* scales = (const float*)d_in[2];
    const float* up     = (const float*)d_in[3];
    const float* down   = (const float*)d_in[4];
    const float* alpha  = (const float*)d_in[5];
    const float* bias   = (const float*)d_in[6];
    float* y = (float*)d_out;
    (void)in_sizes; (void)n_in; (void)out_size;

    // 1) x -> fp16  AND  y = bias (broadcast init)
    cvt_init_kernel<<<2 * CVT_BLOCKS, 256>>>(x, bias, y);
    // 2) dequant + LoRA -> fp16 W (o-tile 8)
    prep_w_kernel<<<((I_DIM / 4) * (O_DIM / 8)) / 256, 256>>>(q, scales, up, down, alpha);
    // 3) persistent split-K fp16 tensor-core GEMM (atomic accumulate into y)
    cudaFuncSetAttribute(gemm_kernel, cudaFuncAttributeMaxDynamicSharedMemorySize,
                         DYN_SMEM_BYTES);
    gemm_kernel<<<NCTA, 256, DYN_SMEM_BYTES>>>(y);
}

// round 15
// speedup vs baseline: 1.7293x; 1.0151x over previous
#include <cuda_runtime.h>
#include <cuda_fp16.h>
#include <cstdint>

// Problem dims (fixed by the dataset)
#define T_DIM 2048
#define O_DIM 4096
#define I_DIM 4096
#define R_DIM 16
#define QB    32

// Scratch: fp16 copies of W (dequant + LoRA folded) and x.
__device__ __align__(16) __half g_Wh[(size_t)O_DIM * I_DIM]; // 32 MB
__device__ __align__(16) __half g_Xh[(size_t)T_DIM * I_DIM]; // 16 MB

// ---------------------------------------------------------------------------
// Kernel 1 (merged prep):
//   blocks [0,2048)      : W_fp16 = (q-8)*scale + alpha*up@down  (longest first)
//   blocks [2048,6144)   : x fp32 -> fp16 (8 elems/thread)
//   blocks [6144,10240)  : y[t,o] = bias[o]  (pre-init for atomic GEMM)
// ---------------------------------------------------------------------------
#define PREP_BLOCKS 2048
#define CVT_BLOCKS  4096
#define INIT_BLOCKS 4096

__global__ void prep_all_kernel(const float* __restrict__ x,
                                const int* __restrict__ q,
                                const float* __restrict__ scales,
                                const float* __restrict__ up,
                                const float* __restrict__ down,
                                const float* __restrict__ alpha_p,
                                const float* __restrict__ bias,
                                float* __restrict__ y) {
    const unsigned b = blockIdx.x;
    if (b >= PREP_BLOCKS) {
        if (b < PREP_BLOCKS + CVT_BLOCKS) {
            // ---- x -> fp16
            size_t i = ((size_t)(b - PREP_BLOCKS) * blockDim.x + threadIdx.x) * 8;
            float4 v0 = *(const float4*)(x + i);
            float4 v1 = *(const float4*)(x + i + 4);
            *(__half2*)(g_Xh + i)     = __floats2half2_rn(v0.x, v0.y);
            *(__half2*)(g_Xh + i + 2) = __floats2half2_rn(v0.z, v0.w);
            *(__half2*)(g_Xh + i + 4) = __floats2half2_rn(v1.x, v1.y);
            *(__half2*)(g_Xh + i + 6) = __floats2half2_rn(v1.z, v1.w);
        } else {
            // ---- y = bias (row-broadcast)
            size_t i = ((size_t)(b - PREP_BLOCKS - CVT_BLOCKS) * blockDim.x
                        + threadIdx.x) * 8;
            int o = (int)(i & (O_DIM - 1));      // 8-aligned within a row
            float4 b0 = *(const float4*)(bias + o);
            float4 b1 = *(const float4*)(bias + o + 4);
            *(float4*)(y + i)     = b0;
            *(float4*)(y + i + 4) = b1;
        }
        return;
    }

    // ---- W_fp16[o,i] = (q-8)*scale + alpha * up@down  (o-tile 8, i-tile 4)
    const int igroups = I_DIM / 4; // 1024
    size_t gt = (size_t)b * blockDim.x + threadIdx.x;
    int ig = (int)(gt % igroups);
    int ob = (int)(gt / igroups) * 8;
    int i  = ig * 4;
    float alpha = *alpha_p;

    float4 dsum[8];
#pragma unroll
    for (int j = 0; j < 8; ++j) dsum[j] = make_float4(0.f, 0.f, 0.f, 0.f);

#pragma unroll
    for (int r = 0; r < R_DIM; ++r) {
        float4 dv = *(const float4*)(down + (size_t)r * I_DIM + i);
#pragma unroll
        for (int j = 0; j < 8; ++j) {
            float u = up[(size_t)(ob + j) * R_DIM + r];
            dsum[j].x += u * dv.x;
            dsum[j].y += u * dv.y;
            dsum[j].z += u * dv.z;
            dsum[j].w += u * dv.w;
        }
    }

#pragma unroll
    for (int j = 0; j < 8; ++j) {
        int o = ob + j;
        size_t base = (size_t)o * I_DIM + i;
        int4 qv = *(const int4*)(q + base);
        float s = scales[(size_t)o * (I_DIM / QB) + (i >> 5)];
        float w0 = (float)(qv.x - 8) * s + alpha * dsum[j].x;
        float w1 = (float)(qv.y - 8) * s + alpha * dsum[j].y;
        float w2 = (float)(qv.z - 8) * s + alpha * dsum[j].z;
        float w3 = (float)(qv.w - 8) * s + alpha * dsum[j].w;
        *(__half2*)(g_Wh + base)     = __floats2half2_rn(w0, w1);
        *(__half2*)(g_Wh + base + 2) = __floats2half2_rn(w2, w3);
    }
}

// ---------------------------------------------------------------------------
// Kernel 2: PERSISTENT split-K GEMM,  y += Xh * Wh^T  (y pre-init to bias).
// (R14 kernel verbatim — measured within 8% of the HMMA accept-rate floor.)
// 148 CTAs (1/SM). Work = 16384 units (256 tiles x 64 k-tiles); contiguous
// ~110.7-unit ranges; tile K may split across CTAs -> f32 atomicAdd epilogue.
// CTA tile 128x256x64, 8 warps (2M x 4N), warp tile 64x64, 4 stages.
// ---------------------------------------------------------------------------
#define GBM 128
#define GBN 256
#define GBK 64
#define NKT (I_DIM / GBK)        // 64
#define NTILES ((T_DIM / GBM) * (O_DIM / GBN))  // 256
#define UNITS (NTILES * NKT)     // 16384
#define NCTA 148
#define LDSH 72                  // halves per smem row (144 B, conflict-free)
#define A_STAGE_H (GBM * LDSH)
#define B_STAGE_H (GBN * LDSH)
#define STAGE_H   (A_STAGE_H + B_STAGE_H)
#define NSTAGE 4
#define DYN_SMEM_BYTES (NSTAGE * STAGE_H * 2)  // 221,184 B

__device__ __forceinline__ uint32_t smem_u32(const void* p) {
    return (uint32_t)__cvta_generic_to_shared(p);
}
__device__ __forceinline__ void cp_async16(uint32_t s, const void* g) {
    asm volatile("cp.async.cg.shared.global [%0], [%1], 16;" :: "r"(s), "l"(g));
}
__device__ __forceinline__ void ldsm_x4(uint32_t* r, uint32_t addr) {
    asm volatile("ldmatrix.sync.aligned.m8n8.x4.shared.b16 {%0,%1,%2,%3}, [%4];"
                 : "=r"(r[0]), "=r"(r[1]), "=r"(r[2]), "=r"(r[3]) : "r"(addr));
}
__device__ __forceinline__ void mma_16816(float* c, const uint32_t* a, const uint32_t* b) {
    asm volatile(
        "mma.sync.aligned.m16n8k16.row.col.f32.f16.f16.f32 "
        "{%0,%1,%2,%3}, {%4,%5,%6,%7}, {%8,%9}, {%0,%1,%2,%3};\n"
        : "+f"(c[0]), "+f"(c[1]), "+f"(c[2]), "+f"(c[3])
        : "r"(a[0]), "r"(a[1]), "r"(a[2]), "r"(a[3]), "r"(b[0]), "r"(b[1]));
}

__global__ void __launch_bounds__(256, 1) gemm_kernel(float* __restrict__ y) {
    extern __shared__ __half smem[];

    const int tid  = threadIdx.x;
    const int lane = tid & 31;
    const int warp = tid >> 5;
    const int wm = warp >> 2;  // 0..1 (M)
    const int wn = warp & 3;   // 0..3 (N)

    const int u0 = (int)(((long long)blockIdx.x * UNITS) / NCTA);
    const int u1 = (int)(((long long)(blockIdx.x + 1) * UNITS) / NCTA);

    const int ach = (tid & 7) * 8;

    auto issue_stage = [&](int u) {
        const int stg  = u & 3;
        const int tile = u >> 6;
        const int kt   = u & 63;
        const __half* gAk = g_Xh + (size_t)(tile >> 4) * GBM * I_DIM + kt * GBK;
        const __half* gBk = g_Wh + (size_t)(tile & 15) * GBN * I_DIM + kt * GBK;
        __half* sa = smem + stg * STAGE_H;
        __half* sb = sa + A_STAGE_H;
#pragma unroll
        for (int j = 0; j < 4; ++j) {
            int row = (tid >> 3) + j * 32;       // 0..127
            cp_async16(smem_u32(sa + row * LDSH + ach),
                       gAk + (size_t)row * I_DIM + ach);
        }
#pragma unroll
        for (int j = 0; j < 8; ++j) {
            int row = (tid >> 3) + j * 32;       // 0..255
            cp_async16(smem_u32(sb + row * LDSH + ach),
                       gBk + (size_t)row * I_DIM + ach);
        }
    };

    float acc[4][8][4];
#pragma unroll
    for (int a = 0; a < 4; ++a)
#pragma unroll
        for (int b = 0; b < 8; ++b)
#pragma unroll
            for (int c = 0; c < 4; ++c) acc[a][b][c] = 0.f;

    const int gid = lane >> 2, tig = lane & 3;
    auto epilogue = [&](int tile) {
        const size_t bmOff = (size_t)(tile >> 4) * GBM;
        const size_t bnOff = (size_t)(tile & 15) * GBN;
#pragma unroll
        for (int mi = 0; mi < 4; ++mi) {
            const size_t row = bmOff + wm * 64 + mi * 16 + gid;
            float* y0 = y + row * O_DIM;
            float* y1 = y + (row + 8) * O_DIM;
#pragma unroll
            for (int ni = 0; ni < 8; ++ni) {
                const int col = (int)bnOff + wn * 64 + ni * 8 + tig * 2;
                atomicAdd(y0 + col,     acc[mi][ni][0]);
                atomicAdd(y0 + col + 1, acc[mi][ni][1]);
                atomicAdd(y1 + col,     acc[mi][ni][2]);
                atomicAdd(y1 + col + 1, acc[mi][ni][3]);
                acc[mi][ni][0] = 0.f; acc[mi][ni][1] = 0.f;
                acc[mi][ni][2] = 0.f; acc[mi][ni][3] = 0.f;
            }
        }
    };

    // prologue: fill 3 stages
    issue_stage(u0);
    asm volatile("cp.async.commit_group;" ::: "memory");
    if (u0 + 1 < u1) issue_stage(u0 + 1);
    asm volatile("cp.async.commit_group;" ::: "memory");
    if (u0 + 2 < u1) issue_stage(u0 + 2);
    asm volatile("cp.async.commit_group;" ::: "memory");

    const int a_r = (lane & 15);
    const int a_c = (lane >> 4) * 8;
    const int bg  = lane >> 3;                     // 0..3
    const int b_r = ((bg >> 1) * 8) + (lane & 7);
    const int b_c = (bg & 1) * 8;

    uint32_t afr[2][4][4];
    uint32_t bfr[2][8][2];

    auto load_frags = [&](const __half* sa, const __half* sb, int ks, int buf) {
#pragma unroll
        for (int mi = 0; mi < 4; ++mi) {
            uint32_t ad = smem_u32(sa + (wm * 64 + mi * 16 + a_r) * LDSH
                                      + ks * 16 + a_c);
            ldsm_x4(afr[buf][mi], ad);
        }
#pragma unroll
        for (int nq = 0; nq < 4; ++nq) {
            uint32_t r[4];
            uint32_t bd = smem_u32(sb + (wn * 64 + nq * 16 + b_r) * LDSH
                                      + ks * 16 + b_c);
            ldsm_x4(r, bd);
            bfr[buf][nq * 2 + 0][0] = r[0]; bfr[buf][nq * 2 + 0][1] = r[1];
            bfr[buf][nq * 2 + 1][0] = r[2]; bfr[buf][nq * 2 + 1][1] = r[3];
        }
    };

    for (int u = u0; u < u1; ++u) {
        const int stg = u & 3;
        asm volatile("cp.async.wait_group 2;" ::: "memory");
        __syncthreads();

        if (u + 3 < u1) issue_stage(u + 3);
        asm volatile("cp.async.commit_group;" ::: "memory");

        if (u != u0 && (u & 63) == 0)
            epilogue((u >> 6) - 1);

        const __half* sa = smem + stg * STAGE_H;
        const __half* sb = sa + A_STAGE_H;

        load_frags(sa, sb, 0, 0);
#pragma unroll
        for (int ks = 0; ks < 4; ++ks) {
            const int cur = ks & 1;
            if (ks < 3) load_frags(sa, sb, ks + 1, cur ^ 1);
#pragma unroll
            for (int mi = 0; mi < 4; ++mi)
#pragma unroll
                for (int ni = 0; ni < 8; ++ni)
                    mma_16816(acc[mi][ni], afr[cur][mi], bfr[cur][ni]);
        }
    }

    epilogue((u1 - 1) >> 6);
}

// ---------------------------------------------------------------------------
extern "C" void kernel_launch(void* const* d_in, const int* in_sizes, int n_in,
                              void* d_out, int out_size) {
    const float* x      = (const float*)d_in[0];
    const int*   q      = (const int*)d_in[1];
    const float* scales = (const float*)d_in[2];
    const float* up     = (const float*)d_in[3];
    const float* down   = (const float*)d_in[4];
    const float* alpha  = (const float*)d_in[5];
    const float* bias   = (const float*)d_in[6];
    float* y = (float*)d_out;
    (void)in_sizes; (void)n_in; (void)out_size;

    // 1) merged: W dequant+LoRA, x->fp16, y=bias   (prep blocks first)
    prep_all_kernel<<<PREP_BLOCKS + CVT_BLOCKS + INIT_BLOCKS, 256>>>(
        x, q, scales, up, down, alpha, bias, y);
    // 2) persistent split-K fp16 tensor-core GEMM (atomic accumulate into y)
    cudaFuncSetAttribute(gemm_kernel, cudaFuncAttributeMaxDynamicSharedMemorySize,
                         DYN_SMEM_BYTES);
    gemm_kernel<<<NCTA, 256, DYN_SMEM_BYTES>>>(y);
}

// round 16
// speedup vs baseline: 1.7886x; 1.0343x over previous
#include <cuda_runtime.h>
#include <cuda_fp16.h>
#include <cstdint>

// Problem dims (fixed by the dataset)
#define T_DIM 2048
#define O_DIM 4096
#define I_DIM 4096
#define R_DIM 16
#define QB    32

// Scratch: fp16 copies of W (dequant + LoRA folded) and x.
__device__ __align__(16) __half g_Wh[(size_t)O_DIM * I_DIM]; // 32 MB
__device__ __align__(16) __half g_Xh[(size_t)T_DIM * I_DIM]; // 16 MB

// ---------------------------------------------------------------------------
// Kernel 1 (merged prep):
//   blocks [0,2048)      : W_fp16 = (q-8)*scale + alpha*up@down  (longest first)
//   blocks [2048,6144)   : x fp32 -> fp16 (8 elems/thread)
//   blocks [6144,10240)  : y[t,o] = bias[o]  (pre-init for atomic GEMM)
// ---------------------------------------------------------------------------
#define PREP_BLOCKS 2048
#define CVT_BLOCKS  4096
#define INIT_BLOCKS 4096

__global__ void prep_all_kernel(const float* __restrict__ x,
                                const int* __restrict__ q,
                                const float* __restrict__ scales,
                                const float* __restrict__ up,
                                const float* __restrict__ down,
                                const float* __restrict__ alpha_p,
                                const float* __restrict__ bias,
                                float* __restrict__ y) {
    const unsigned b = blockIdx.x;
    if (b >= PREP_BLOCKS) {
        if (b < PREP_BLOCKS + CVT_BLOCKS) {
            size_t i = ((size_t)(b - PREP_BLOCKS) * blockDim.x + threadIdx.x) * 8;
            float4 v0 = *(const float4*)(x + i);
            float4 v1 = *(const float4*)(x + i + 4);
            *(__half2*)(g_Xh + i)     = __floats2half2_rn(v0.x, v0.y);
            *(__half2*)(g_Xh + i + 2) = __floats2half2_rn(v0.z, v0.w);
            *(__half2*)(g_Xh + i + 4) = __floats2half2_rn(v1.x, v1.y);
            *(__half2*)(g_Xh + i + 6) = __floats2half2_rn(v1.z, v1.w);
        } else {
            size_t i = ((size_t)(b - PREP_BLOCKS - CVT_BLOCKS) * blockDim.x
                        + threadIdx.x) * 8;
            int o = (int)(i & (O_DIM - 1));
            float4 b0 = *(const float4*)(bias + o);
            float4 b1 = *(const float4*)(bias + o + 4);
            *(float4*)(y + i)     = b0;
            *(float4*)(y + i + 4) = b1;
        }
        return;
    }

    const int igroups = I_DIM / 4; // 1024
    size_t gt = (size_t)b * blockDim.x + threadIdx.x;
    int ig = (int)(gt % igroups);
    int ob = (int)(gt / igroups) * 8;
    int i  = ig * 4;
    float alpha = *alpha_p;

    float4 dsum[8];
#pragma unroll
    for (int j = 0; j < 8; ++j) dsum[j] = make_float4(0.f, 0.f, 0.f, 0.f);

#pragma unroll
    for (int r = 0; r < R_DIM; ++r) {
        float4 dv = *(const float4*)(down + (size_t)r * I_DIM + i);
#pragma unroll
        for (int j = 0; j < 8; ++j) {
            float u = up[(size_t)(ob + j) * R_DIM + r];
            dsum[j].x += u * dv.x;
            dsum[j].y += u * dv.y;
            dsum[j].z += u * dv.z;
            dsum[j].w += u * dv.w;
        }
    }

#pragma unroll
    for (int j = 0; j < 8; ++j) {
        int o = ob + j;
        size_t base = (size_t)o * I_DIM + i;
        int4 qv = *(const int4*)(q + base);
        float s = scales[(size_t)o * (I_DIM / QB) + (i >> 5)];
        float w0 = (float)(qv.x - 8) * s + alpha * dsum[j].x;
        float w1 = (float)(qv.y - 8) * s + alpha * dsum[j].y;
        float w2 = (float)(qv.z - 8) * s + alpha * dsum[j].z;
        float w3 = (float)(qv.w - 8) * s + alpha * dsum[j].w;
        *(__half2*)(g_Wh + base)     = __floats2half2_rn(w0, w1);
        *(__half2*)(g_Wh + base + 2) = __floats2half2_rn(w2, w3);
    }
}

// ---------------------------------------------------------------------------
// Kernel 2: PERSISTENT split-K GEMM,  y += Xh * Wh^T  (y pre-init to bias).
// R16 change: cross-barrier fragment preload — frags for (u+1, ks0) are
// loaded at the END of iteration u (data guaranteed by wait_group 1), so the
// post-barrier path goes straight into mma with resident operands.
// 148 CTAs, CTA tile 128x256x64, 8 warps (2M x 4N), warp tile 64x64, 4 stages.
// ---------------------------------------------------------------------------
#define GBM 128
#define GBN 256
#define GBK 64
#define NKT (I_DIM / GBK)        // 64
#define NTILES ((T_DIM / GBM) * (O_DIM / GBN))  // 256
#define UNITS (NTILES * NKT)     // 16384
#define NCTA 148
#define LDSH 72                  // halves per smem row (144 B, conflict-free)
#define A_STAGE_H (GBM * LDSH)
#define B_STAGE_H (GBN * LDSH)
#define STAGE_H   (A_STAGE_H + B_STAGE_H)
#define NSTAGE 4
#define DYN_SMEM_BYTES (NSTAGE * STAGE_H * 2)  // 221,184 B

__device__ __forceinline__ uint32_t smem_u32(const void* p) {
    return (uint32_t)__cvta_generic_to_shared(p);
}
__device__ __forceinline__ void cp_async16(uint32_t s, const void* g) {
    asm volatile("cp.async.cg.shared.global [%0], [%1], 16;" :: "r"(s), "l"(g));
}
__device__ __forceinline__ void ldsm_x4(uint32_t* r, uint32_t addr) {
    asm volatile("ldmatrix.sync.aligned.m8n8.x4.shared.b16 {%0,%1,%2,%3}, [%4];"
                 : "=r"(r[0]), "=r"(r[1]), "=r"(r[2]), "=r"(r[3]) : "r"(addr));
}
__device__ __forceinline__ void mma_16816(float* c, const uint32_t* a, const uint32_t* b) {
    asm volatile(
        "mma.sync.aligned.m16n8k16.row.col.f32.f16.f16.f32 "
        "{%0,%1,%2,%3}, {%4,%5,%6,%7}, {%8,%9}, {%0,%1,%2,%3};\n"
        : "+f"(c[0]), "+f"(c[1]), "+f"(c[2]), "+f"(c[3])
        : "r"(a[0]), "r"(a[1]), "r"(a[2]), "r"(a[3]), "r"(b[0]), "r"(b[1]));
}

__global__ void __launch_bounds__(256, 1) gemm_kernel(float* __restrict__ y) {
    extern __shared__ __half smem[];

    const int tid  = threadIdx.x;
    const int lane = tid & 31;
    const int warp = tid >> 5;
    const int wm = warp >> 2;  // 0..1 (M)
    const int wn = warp & 3;   // 0..3 (N)

    const int u0 = (int)(((long long)blockIdx.x * UNITS) / NCTA);
    const int u1 = (int)(((long long)(blockIdx.x + 1) * UNITS) / NCTA);

    const int ach = (tid & 7) * 8;

    auto issue_stage = [&](int u) {
        const int stg  = u & 3;
        const int tile = u >> 6;
        const int kt   = u & 63;
        const __half* gAk = g_Xh + (size_t)(tile >> 4) * GBM * I_DIM + kt * GBK;
        const __half* gBk = g_Wh + (size_t)(tile & 15) * GBN * I_DIM + kt * GBK;
        __half* sa = smem + stg * STAGE_H;
        __half* sb = sa + A_STAGE_H;
#pragma unroll
        for (int j = 0; j < 4; ++j) {
            int row = (tid >> 3) + j * 32;       // 0..127
            cp_async16(smem_u32(sa + row * LDSH + ach),
                       gAk + (size_t)row * I_DIM + ach);
        }
#pragma unroll
        for (int j = 0; j < 8; ++j) {
            int row = (tid >> 3) + j * 32;       // 0..255
            cp_async16(smem_u32(sb + row * LDSH + ach),
                       gBk + (size_t)row * I_DIM + ach);
        }
    };

    float acc[4][8][4];
#pragma unroll
    for (int a = 0; a < 4; ++a)
#pragma unroll
        for (int b = 0; b < 8; ++b)
#pragma unroll
            for (int c = 0; c < 4; ++c) acc[a][b][c] = 0.f;

    const int gid = lane >> 2, tig = lane & 3;
    auto epilogue = [&](int tile) {
        const size_t bmOff = (size_t)(tile >> 4) * GBM;
        const size_t bnOff = (size_t)(tile & 15) * GBN;
#pragma unroll
        for (int mi = 0; mi < 4; ++mi) {
            const size_t row = bmOff + wm * 64 + mi * 16 + gid;
            float* y0 = y + row * O_DIM;
            float* y1 = y + (row + 8) * O_DIM;
#pragma unroll
            for (int ni = 0; ni < 8; ++ni) {
                const int col = (int)bnOff + wn * 64 + ni * 8 + tig * 2;
                atomicAdd(y0 + col,     acc[mi][ni][0]);
                atomicAdd(y0 + col + 1, acc[mi][ni][1]);
                atomicAdd(y1 + col,     acc[mi][ni][2]);
                atomicAdd(y1 + col + 1, acc[mi][ni][3]);
                acc[mi][ni][0] = 0.f; acc[mi][ni][1] = 0.f;
                acc[mi][ni][2] = 0.f; acc[mi][ni][3] = 0.f;
            }
        }
    };

    // ldsm lane addressing
    const int a_r = (lane & 15);
    const int a_c = (lane >> 4) * 8;
    const int bg  = lane >> 3;                     // 0..3
    const int b_r = ((bg >> 1) * 8) + (lane & 7);
    const int b_c = (bg & 1) * 8;

    uint32_t afr[2][4][4];
    uint32_t bfr[2][8][2];

    auto load_frags = [&](const __half* sa, const __half* sb, int ks, int buf) {
#pragma unroll
        for (int mi = 0; mi < 4; ++mi) {
            uint32_t ad = smem_u32(sa + (wm * 64 + mi * 16 + a_r) * LDSH
                                      + ks * 16 + a_c);
            ldsm_x4(afr[buf][mi], ad);
        }
#pragma unroll
        for (int nq = 0; nq < 4; ++nq) {
            uint32_t r[4];
            uint32_t bd = smem_u32(sb + (wn * 64 + nq * 16 + b_r) * LDSH
                                      + ks * 16 + b_c);
            ldsm_x4(r, bd);
            bfr[buf][nq * 2 + 0][0] = r[0]; bfr[buf][nq * 2 + 0][1] = r[1];
            bfr[buf][nq * 2 + 1][0] = r[2]; bfr[buf][nq * 2 + 1][1] = r[3];
        }
    };

    auto stage_ptr = [&](int u) -> const __half* { return smem + (u & 3) * STAGE_H; };

    // prologue: fill 3 stages, then preload frags for (u0, ks0)
    issue_stage(u0);
    asm volatile("cp.async.commit_group;" ::: "memory");
    issue_stage(u0 + 1);
    asm volatile("cp.async.commit_group;" ::: "memory");
    issue_stage(u0 + 2);
    asm volatile("cp.async.commit_group;" ::: "memory");
    asm volatile("cp.async.wait_group 2;" ::: "memory");   // u0 resident
    __syncthreads();                                        // cross-thread visibility
    load_frags(stage_ptr(u0), stage_ptr(u0) + A_STAGE_H, 0, 0);

    for (int u = u0; u < u1; ++u) {
        // flush previous tile's partial sums at tile boundary
        if (u != u0 && (u & 63) == 0)
            epilogue((u >> 6) - 1);

        const __half* sa = stage_ptr(u);
        const __half* sb = sa + A_STAGE_H;

        // mma body: ks0 frags already resident (preloaded last iteration)
#pragma unroll
        for (int ks = 0; ks < 4; ++ks) {
            const int cur = ks & 1;
            if (ks < 3) load_frags(sa, sb, ks + 1, cur ^ 1);
#pragma unroll
            for (int mi = 0; mi < 4; ++mi)
#pragma unroll
                for (int ni = 0; ni < 8; ++ni)
                    mma_16816(acc[mi][ni], afr[cur][mi], bfr[cur][ni]);
        }

        if (u + 1 < u1) {
            // in-flight: {u+1, u+2}; wait_group 1 -> u+1 data complete
            asm volatile("cp.async.wait_group 1;" ::: "memory");
            __syncthreads();   // visibility of all threads' u+1 copies;
                               // also guards issue_stage's rewrite of stage (u-1)
            // preload next unit's ks0 into buf0 (ks parity: 4 ks -> ks0 = buf0)
            load_frags(stage_ptr(u + 1), stage_ptr(u + 1) + A_STAGE_H, 0, 0);
            if (u + 3 < u1) issue_stage(u + 3);
            asm volatile("cp.async.commit_group;" ::: "memory");
        }
    }

    epilogue((u1 - 1) >> 6);
}

// ---------------------------------------------------------------------------
extern "C" void kernel_launch(void* const* d_in, const int* in_sizes, int n_in,
                              void* d_out, int out_size) {
    const float* x      = (const float*)d_in[0];
    const int*   q      = (const int*)d_in[1];
    const float* scales = (const float*)d_in[2];
    const float* up     = (const float*)d_in[3];
    const float* down   = (const float*)d_in[4];
    const float* alpha  = (const float*)d_in[5];
    const float* bias   = (const float*)d_in[6];
    float* y = (float*)d_out;
    (void)in_sizes; (void)n_in; (void)out_size;

    // 1) merged: W dequant+LoRA, x->fp16, y=bias   (prep blocks first)
    prep_all_kernel<<<PREP_BLOCKS + CVT_BLOCKS + INIT_BLOCKS, 256>>>(
        x, q, scales, up, down, alpha, bias, y);
    // 2) persistent split-K fp16 tensor-core GEMM (atomic accumulate into y)
    cudaFuncSetAttribute(gemm_kernel, cudaFuncAttributeMaxDynamicSharedMemorySize,
                         DYN_SMEM_BYTES);
    gemm_kernel<<<NCTA, 256, DYN_SMEM_BYTES>>>(y);
}